// round 7
// baseline (speedup 1.0000x reference)
#include <cuda_runtime.h>
#include <math.h>

#define NCTA 256   // 128 unit-pairs x 2 batch-halves
#define NTH  512
#define Bsz  256
#define Tlen 1024
#define Hdim 256
#define K2n  128   // Hdim/2 k-pairs (f32x2 lanes = k-pairs)
#define K2PT 32    // K2n / 4 k-split groups

// Persistent state, exchanged through L2 (double-buffered by step parity).
// u64 layout: [k2][b] packs {h[2k2][b], h[2k2+1][b]}.
__device__ unsigned long long g_h0p[2][K2n * Bsz];
__device__ unsigned long long g_h1p[2][K2n * Bsz];
__device__ float g_xT[Tlen * Bsz];   // x transposed: [t][b]
__device__ unsigned g_cntA = 0;      // barrier line A (h0 publishes)
__device__ unsigned g_cntB = 0;      // barrier line B (h1 publishes)
__device__ unsigned g_done = 0;      // end-of-kernel reset rendezvous

union F2U { float2 f; unsigned long long u; };

__device__ __forceinline__ unsigned long long pack2(float a, float b) {
    F2U v; v.f.x = a; v.f.y = b; return v.u;
}
__device__ __forceinline__ float2 unpack2(unsigned long long u) {
    F2U v; v.u = u; return v.f;
}
// Blackwell packed fp32x2 FMA: 2 exact fp32 MACs per instruction.
__device__ __forceinline__ unsigned long long ffma2(unsigned long long a,
                                                    unsigned long long b,
                                                    unsigned long long c) {
    unsigned long long d;
    asm("fma.rn.f32x2 %0, %1, %2, %3;" : "=l"(d) : "l"(a), "l"(b), "l"(c));
    return d;
}
__device__ __forceinline__ float redsum(unsigned long long a) {
    float2 v = unpack2(a); return v.x + v.y;
}
__device__ __forceinline__ float sigf(float x) {
    return __fdividef(1.0f, 1.0f + __expf(-x));
}
__device__ __forceinline__ float tanhf_(float x) {
    return fmaf(2.0f, sigf(2.0f * x), -1.0f);
}

// Split-phase grid barrier (NCTA co-resident CTAs, 2/SM).
__device__ __forceinline__ void bar_arrive(unsigned* c) {
    __syncthreads();                       // CTA's stores done
    if (threadIdx.x == 0) { __threadfence(); atomicAdd(c, 1u); }
}
__device__ __forceinline__ void bar_wait(unsigned* c, unsigned target) {
    if (threadIdx.x == 0) {
        unsigned v;
        do {
            asm volatile("ld.acquire.gpu.u32 %0, [%1];" : "=r"(v) : "l"(c));
        } while (v < target);
    }
    __syncthreads();
}

// ---- layer-0 matvec slice: writes per-(j,b) gate partials to sRed ----
__device__ __forceinline__ void mv_l0(const unsigned long long* __restrict__ hp,
                                      const ulonglong2* __restrict__ sW,
                                      float4* __restrict__ sRed,
                                      int bg, int bloc, int ks, int k0) {
    unsigned long long acc[4][2];
    #pragma unroll
    for (int q = 0; q < 4; ++q) { acc[q][0] = 0ull; acc[q][1] = 0ull; }
    #pragma unroll 4
    for (int i = 0; i < K2PT; ++i) {
        int k2 = k0 + i;
        unsigned long long h = __ldcg(hp + k2 * Bsz + bg);
        #pragma unroll
        for (int q = 0; q < 4; ++q) {
            ulonglong2 w = sW[k2 * 4 + q];           // broadcast LDS.128
            acc[q][0] = ffma2(h, w.x, acc[q][0]);
            acc[q][1] = ffma2(h, w.y, acc[q][1]);
        }
    }
    #pragma unroll
    for (int j = 0; j < 2; ++j)
        sRed[(ks * 2 + j) * 128 + bloc] =
            make_float4(redsum(acc[0][j]), redsum(acc[1][j]),
                        redsum(acc[2][j]), redsum(acc[3][j]));
}

// ---- layer-1 matvec slice (two input matrices) ----
__device__ __forceinline__ void mv_l1(const unsigned long long* __restrict__ ha,
                                      const unsigned long long* __restrict__ hb,
                                      const ulonglong2* __restrict__ sWi,
                                      const ulonglong2* __restrict__ sWh,
                                      float4* __restrict__ sRed,
                                      int bg, int bloc, int ks, int k0) {
    unsigned long long acc[4][2];
    #pragma unroll
    for (int q = 0; q < 4; ++q) { acc[q][0] = 0ull; acc[q][1] = 0ull; }
    #pragma unroll 4
    for (int i = 0; i < K2PT; ++i) {
        int k2 = k0 + i;
        unsigned long long va = __ldcg(ha + k2 * Bsz + bg);
        unsigned long long vb = __ldcg(hb + k2 * Bsz + bg);
        #pragma unroll
        for (int q = 0; q < 4; ++q) {
            ulonglong2 wi = sWi[k2 * 4 + q];
            ulonglong2 wh = sWh[k2 * 4 + q];
            acc[q][0] = ffma2(va, wi.x, acc[q][0]);
            acc[q][1] = ffma2(va, wi.y, acc[q][1]);
            acc[q][0] = ffma2(vb, wh.x, acc[q][0]);
            acc[q][1] = ffma2(vb, wh.y, acc[q][1]);
        }
    }
    #pragma unroll
    for (int j = 0; j < 2; ++j)
        sRed[(ks * 2 + j) * 128 + bloc] =
            make_float4(redsum(acc[0][j]), redsum(acc[1][j]),
                        redsum(acc[2][j]), redsum(acc[3][j]));
}

__global__ void __launch_bounds__(NTH, 2)
lstm_fused(const float* __restrict__ x,
           const float* __restrict__ Wih0, const float* __restrict__ Whh0,
           const float* __restrict__ bih0, const float* __restrict__ bhh0,
           const float* __restrict__ Wih1, const float* __restrict__ Whh1,
           const float* __restrict__ bih1, const float* __restrict__ bhh1,
           const float* __restrict__ Wlin, const float* __restrict__ blin,
           float* __restrict__ out)
{
    __shared__ ulonglong2 sW0 [K2n * 4];   // 8 KB each, pair-packed (k-pair lanes)
    __shared__ ulonglong2 sW1i[K2n * 4];
    __shared__ ulonglong2 sW1h[K2n * 4];
    __shared__ float4 sRed[8 * 128];       // 16 KB: [ks*2 + j][bloc] gate partials
    __shared__ float sWx[8], sB0[8], sB1[8];
    __shared__ float sWlin[Hdim];
    __shared__ float sOut[4];

    const int tid  = threadIdx.x;
    const int bloc = tid & 127;            // batch within this CTA's half
    const int ks   = tid >> 7;             // k-split group 0..3 (warp-uniform)
    const int cta  = blockIdx.x;
    const int up   = cta >> 1;             // owned unit-pair index
    const int bh   = cta & 1;              // batch half
    const int u0   = 2 * up;
    const int bg   = bh * 128 + bloc;      // global batch this thread loads
    const int k0   = ks * K2PT;
    const int bout = cta;                  // batch whose output this CTA emits

    // activation role (threads 0..255): unit j, batch ab (within half)
    const int aj = tid >> 7;               // valid when tid < 256
    const int ab = tid & 127;
    const int abg = bh * 128 + ab;

    // ---- one-time staging ----
    for (int i = cta * NTH + tid; i < Bsz * Tlen; i += NCTA * NTH) {
        int b = i >> 10, t = i & (Tlen - 1);
        g_xT[t * Bsz + b] = x[i];
    }
    for (int e = tid; e < K2n * 4; e += NTH) {
        int k2 = e >> 2, q = e & 3;
        int base = (q * Hdim + u0) * Hdim + 2 * k2;
        sW0[e]  = make_ulonglong2(pack2(Whh0[base],        Whh0[base + 1]),
                                  pack2(Whh0[base + Hdim], Whh0[base + Hdim + 1]));
        sW1i[e] = make_ulonglong2(pack2(Wih1[base],        Wih1[base + 1]),
                                  pack2(Wih1[base + Hdim], Wih1[base + Hdim + 1]));
        sW1h[e] = make_ulonglong2(pack2(Whh1[base],        Whh1[base + 1]),
                                  pack2(Whh1[base + Hdim], Whh1[base + Hdim + 1]));
    }
    if (tid < 8) {
        int q = tid >> 1, j = tid & 1;
        int g = q * Hdim + u0 + j;
        sWx[tid] = Wih0[g];
        sB0[tid] = bih0[g] + bhh0[g];
        sB1[tid] = bih1[g] + bhh1[g];
    }
    if (tid < Hdim) sWlin[tid] = Wlin[tid];
    const float bl = __ldg(blin);

    if (tid < 128) {                       // zero initial state (parity-0), own slice
        g_h0p[0][up * Bsz + bh * 128 + tid] = 0ull;
        g_h1p[0][up * Bsz + bh * 128 + tid] = 0ull;
    }
    float c0 = 0.f, c1 = 0.f;              // cell state (activation threads only)

    // init barrier (line A): staging + zeros visible
    bar_arrive(&g_cntA);
    bar_wait(&g_cntA, 1u * NCTA);

    // ---- prologue: L0(0): h0p[0] -> h0p[1] ----
    {
        mv_l0(g_h0p[0], sW0, sRed, bg, bloc, ks, k0);
        __syncthreads();
        if (tid < 256) {
            float4 s = sRed[(0 * 2 + aj) * 128 + ab];
            #pragma unroll
            for (int g = 1; g < 4; ++g) {
                float4 v = sRed[(g * 2 + aj) * 128 + ab];
                s.x += v.x; s.y += v.y; s.z += v.z; s.w += v.w;
            }
            float xv = g_xT[0 * Bsz + abg];
            float gi = s.x + fmaf(sWx[0*2 + aj], xv, sB0[0*2 + aj]);
            float gf = s.y + fmaf(sWx[1*2 + aj], xv, sB0[1*2 + aj]);
            float gg = s.z + fmaf(sWx[2*2 + aj], xv, sB0[2*2 + aj]);
            float go = s.w + fmaf(sWx[3*2 + aj], xv, sB0[3*2 + aj]);
            float cn = sigf(gf) * c0 + sigf(gi) * tanhf_(gg);
            c0 = cn;
            ((float*)g_h0p[1])[(up * Bsz + abg) * 2 + aj] = sigf(go) * tanhf_(cn);
        }
        bar_arrive(&g_cntA);
        bar_wait(&g_cntA, 2u * NCTA);
    }

    for (int t = 0; t < Tlen; ++t) {
        const int pr = t & 1, nx = pr ^ 1;

        // ---- L1(t): h0p[nx] (new) + h1p[pr] -> h1p[nx] ----
        mv_l1(g_h0p[nx], g_h1p[pr], sW1i, sW1h, sRed, bg, bloc, ks, k0);
        __syncthreads();
        if (tid < 256) {
            float4 s = sRed[(0 * 2 + aj) * 128 + ab];
            #pragma unroll
            for (int g = 1; g < 4; ++g) {
                float4 v = sRed[(g * 2 + aj) * 128 + ab];
                s.x += v.x; s.y += v.y; s.z += v.z; s.w += v.w;
            }
            float gi = s.x + sB1[0*2 + aj];
            float gf = s.y + sB1[1*2 + aj];
            float gg = s.z + sB1[2*2 + aj];
            float go = s.w + sB1[3*2 + aj];
            float cn = sigf(gf) * c1 + sigf(gi) * tanhf_(gg);
            c1 = cn;
            ((float*)g_h1p[nx])[(up * Bsz + abg) * 2 + aj] = sigf(go) * tanhf_(cn);
        }
        bar_arrive(&g_cntB);                 // idB = t+1

        // ---- L0(t+1): h0p[nx] -> h0p[pr]  (hides B-barrier latency) ----
        if (t < Tlen - 1) {
            mv_l0(g_h0p[nx], sW0, sRed, bg, bloc, ks, k0);
            __syncthreads();
            if (tid < 256) {
                float4 s = sRed[(0 * 2 + aj) * 128 + ab];
                #pragma unroll
                for (int g = 1; g < 4; ++g) {
                    float4 v = sRed[(g * 2 + aj) * 128 + ab];
                    s.x += v.x; s.y += v.y; s.z += v.z; s.w += v.w;
                }
                float xv = g_xT[(t + 1) * Bsz + abg];
                float gi = s.x + fmaf(sWx[0*2 + aj], xv, sB0[0*2 + aj]);
                float gf = s.y + fmaf(sWx[1*2 + aj], xv, sB0[1*2 + aj]);
                float gg = s.z + fmaf(sWx[2*2 + aj], xv, sB0[2*2 + aj]);
                float go = s.w + fmaf(sWx[3*2 + aj], xv, sB0[3*2 + aj]);
                float cn = sigf(gf) * c0 + sigf(gi) * tanhf_(gg);
                c0 = cn;
                ((float*)g_h0p[pr])[(up * Bsz + abg) * 2 + aj] = sigf(go) * tanhf_(cn);
            }
            bar_arrive(&g_cntA);             // idA = t+3
        }

        // ---- wait for all h1(t), then output dot for batch `bout` ----
        bar_wait(&g_cntB, (unsigned)(t + 1) * NCTA);
        {
            if (tid < 128) {
                float2 hv = unpack2(__ldcg(&g_h1p[nx][tid * Bsz + bout]));
                float part = hv.x * sWlin[2 * tid] + hv.y * sWlin[2 * tid + 1];
                #pragma unroll
                for (int off = 16; off > 0; off >>= 1)
                    part += __shfl_down_sync(0xffffffffu, part, off);
                if ((tid & 31) == 0) sOut[tid >> 5] = part;
            }
            __syncthreads();
            if (tid == 0)
                out[bout * Tlen + t] = sOut[0] + sOut[1] + sOut[2] + sOut[3] + bl;
        }

        if (t < Tlen - 1)
            bar_wait(&g_cntA, (unsigned)(t + 3) * NCTA);   // h0(t+1) visible
    }

    // reset counters for next launch
    __syncthreads();
    if (tid == 0) {
        __threadfence();
        unsigned old = atomicAdd(&g_done, 1u);
        if (old == NCTA - 1) {
            atomicExch(&g_cntA, 0u);
            atomicExch(&g_cntB, 0u);
            atomicExch(&g_done, 0u);
        }
    }
}

extern "C" void kernel_launch(void* const* d_in, const int* in_sizes, int n_in,
                              void* d_out, int out_size) {
    (void)in_sizes; (void)n_in; (void)out_size;
    lstm_fused<<<NCTA, NTH>>>(
        (const float*)d_in[0],
        (const float*)d_in[1], (const float*)d_in[2],
        (const float*)d_in[3], (const float*)d_in[4],
        (const float*)d_in[5], (const float*)d_in[6],
        (const float*)d_in[7], (const float*)d_in[8],
        (const float*)d_in[9], (const float*)d_in[10],
        (float*)d_out);
}